// round 1
// baseline (speedup 1.0000x reference)
#include <cuda_runtime.h>
#include <math.h>

#define LAYERS 4
#define HIDDEN 512
#define FFND   1024
#define HEADS  4
#define BB     2
#define SSEQ   2048
#define HD     128
#define NROWS  (BB*SSEQ)   // 4096
#define EPS    1e-5f

// ---------------- device scratch (no runtime allocation allowed) ----------------
__device__ float g_X [NROWS*HIDDEN];
__device__ float g_Xn[NROWS*HIDDEN];
__device__ float g_Q [NROWS*HIDDEN];
__device__ float g_K [NROWS*HIDDEN];
__device__ float g_V [NROWS*HIDDEN];
__device__ float g_Yh[NROWS*HIDDEN];
__device__ float g_G [NROWS*HIDDEN];
__device__ float g_P [NROWS*HIDDEN];
__device__ float g_Y [NROWS*HIDDEN];
__device__ float g_Yn[NROWS*HIDDEN];
__device__ float g_F [NROWS*FFND];
__device__ float g_pow[HEADS*SSEQ];
__device__ float g_cu[SSEQ*HD];
__device__ float g_su[SSEQ*HD];
__device__ float g_cd[SSEQ*HD];
__device__ float g_sd[SSEQ*HD];

// ---------------- precompute tables ----------------
__global__ void xpos_tables_kernel(float* cu, float* su, float* cd, float* sd)
{
    int idx = blockIdx.x * blockDim.x + threadIdx.x;
    if (idx >= SSEQ * HD) return;
    int pos = idx / HD;
    int e   = idx % HD;
    int j   = e >> 1;
    float sj = (2.0f * (float)j + 0.4f * (float)HD) / (1.4f * (float)HD);
    double scale = pow((double)sj, (double)pos / 512.0);
    float invf = (float)(1.0 / pow(10000.0, (double)j / 64.0));
    float angf = (float)pos * invf;          // reference rounds ang to f32
    double ang = (double)angf;
    float sn = (float)sin(ang);
    float cs = (float)cos(ang);
    float sc  = (float)scale;
    float isc = (float)(1.0 / scale);
    cu[idx] = cs * sc;  su[idx] = sn * sc;    // Q (upscale)
    cd[idx] = cs * isc; sd[idx] = sn * isc;   // K (downscale)
}

__global__ void pow_kernel(float* powtab)
{
    int idx = blockIdx.x * blockDim.x + threadIdx.x;
    if (idx >= HEADS * SSEQ) return;
    int h = idx / SSEQ;
    int d = idx % SSEQ;
    double lg = log(1.0/32.0) + (double)h * (log(1.0/512.0) - log(1.0/32.0)) / (double)(HEADS - 1);
    double gamma = 1.0 - exp(lg);
    powtab[idx] = (float)exp((double)d * log(gamma));
}

// ---------------- xPos apply (in place, pair-owning threads) ----------------
__global__ void xpos_apply_kernel(float* __restrict__ X,
                                  const float* __restrict__ ct,
                                  const float* __restrict__ st)
{
    int idx = blockIdx.x * blockDim.x + threadIdx.x;   // NROWS*256 pairs
    if (idx >= NROWS * 256) return;
    int r  = idx >> 8;
    int pe = idx & 255;
    int h  = pe >> 6;
    int j  = pe & 63;
    int pos = r & (SSEQ - 1);
    size_t base = (size_t)r * HIDDEN + h * HD + 2 * j;
    float x1 = X[base], x2 = X[base + 1];
    int ti = pos * HD + 2 * j;
    float c = ct[ti], s = st[ti];
    X[base]     = x1 * c - x2 * s;
    X[base + 1] = x2 * c + x1 * s;
}

// ---------------- LayerNorm: one block per row (512) ----------------
__global__ void __launch_bounds__(128) ln_kernel(const float* __restrict__ X,
                                                 const float* __restrict__ w,
                                                 const float* __restrict__ b,
                                                 float* __restrict__ out)
{
    int row = blockIdx.x;
    int tid = threadIdx.x;
    float4 x = *(const float4*)&X[(size_t)row * HIDDEN + tid * 4];
    float s = x.x + x.y + x.z + x.w;
    float q = x.x*x.x + x.y*x.y + x.z*x.z + x.w*x.w;
    #pragma unroll
    for (int o = 16; o > 0; o >>= 1) {
        s += __shfl_xor_sync(0xffffffffu, s, o);
        q += __shfl_xor_sync(0xffffffffu, q, o);
    }
    __shared__ float ss[4], qq[4];
    if ((tid & 31) == 0) { ss[tid >> 5] = s; qq[tid >> 5] = q; }
    __syncthreads();
    float S  = ss[0] + ss[1] + ss[2] + ss[3];
    float Qs = qq[0] + qq[1] + qq[2] + qq[3];
    float mean = S * (1.0f / HIDDEN);
    float var  = Qs * (1.0f / HIDDEN) - mean * mean;
    float inv  = rsqrtf(var + EPS);
    float4 wv = *(const float4*)&w[tid * 4];
    float4 bv = *(const float4*)&b[tid * 4];
    float4 o;
    o.x = (x.x - mean) * inv * wv.x + bv.x;
    o.y = (x.y - mean) * inv * wv.y + bv.y;
    o.z = (x.z - mean) * inv * wv.z + bv.z;
    o.w = (x.w - mean) * inv * wv.w + bv.w;
    *(float4*)&out[(size_t)row * HIDDEN + tid * 4] = o;
}

// ---------------- GroupNorm (4 groups of 128) fused with SiLU gate product ----------------
__global__ void __launch_bounds__(128) gn_gate_kernel(const float* __restrict__ Yh,
                                                      const float* __restrict__ w,
                                                      const float* __restrict__ b,
                                                      const float* __restrict__ G,
                                                      float* __restrict__ P)
{
    int row  = blockIdx.x;
    int tid  = threadIdx.x;
    int wi   = tid >> 5;
    int lane = tid & 31;
    int d = wi * HD + lane * 4;
    float4 y = *(const float4*)&Yh[(size_t)row * HIDDEN + d];
    float s = y.x + y.y + y.z + y.w;
    float q = y.x*y.x + y.y*y.y + y.z*y.z + y.w*y.w;
    #pragma unroll
    for (int o = 16; o > 0; o >>= 1) {
        s += __shfl_xor_sync(0xffffffffu, s, o);
        q += __shfl_xor_sync(0xffffffffu, q, o);
    }
    float mean = s * (1.0f / HD);
    float var  = q * (1.0f / HD) - mean * mean;
    float inv  = rsqrtf(var + EPS);
    float4 wv = *(const float4*)&w[d];
    float4 bv = *(const float4*)&b[d];
    float4 gv = *(const float4*)&G[(size_t)row * HIDDEN + d];
    float4 o;
    o.x = ((y.x - mean) * inv * wv.x + bv.x) * gv.x;
    o.y = ((y.y - mean) * inv * wv.y + bv.y) * gv.y;
    o.z = ((y.z - mean) * inv * wv.z + bv.z) * gv.z;
    o.w = ((y.w - mean) * inv * wv.w + bv.w) * gv.w;
    *(float4*)&P[(size_t)row * HIDDEN + d] = o;
}

// ---------------- generic SGEMM 64x64x16, 256 threads, 4x4 frags ----------------
#define BM 64
#define BN 64
#define BK 16

constexpr int EPI_NONE = 0;
constexpr int EPI_SILU = 1;
constexpr int EPI_RES = 2;
constexpr int EPI_BIAS_GELU = 3;
constexpr int EPI_BIAS_RES = 4;

template<int EPI>
__global__ void __launch_bounds__(256) sgemm_kernel(
    const float* __restrict__ A, const float* __restrict__ Bmat,
    float* __restrict__ C, int M, int N, int K, int headed,
    const float* __restrict__ bias, const float* __restrict__ res)
{
    __shared__ float As[BM][BK];
    __shared__ float Bs[BK][BN];
    int tid = threadIdx.x;
    int tx = tid & 15, ty = tid >> 4;
    int m0 = blockIdx.y * BM;
    int n0 = blockIdx.x * BN;

    const float* Bptr;
    int ldb, ncol;
    if (headed) {   // B[k,n] = W[h, k, e]; tiles never cross head boundary (BN=64, head=128)
        int head = n0 >> 7;
        Bptr = Bmat + (size_t)head * K * HD;
        ldb = HD;
        ncol = n0 & 127;
    } else {
        Bptr = Bmat;
        ldb = N;
        ncol = n0;
    }

    float acc[4][4] = {};
    int arow = tid >> 2, acol = (tid & 3) * 4;     // 64x16 A tile
    int brow = tid >> 4, bcol = (tid & 15) * 4;    // 16x64 B tile

    for (int k0 = 0; k0 < K; k0 += BK) {
        float4 av = *(const float4*)&A[(size_t)(m0 + arow) * K + k0 + acol];
        *(float4*)&As[arow][acol] = av;
        float4 bv = *(const float4*)&Bptr[(size_t)(k0 + brow) * ldb + ncol + bcol];
        *(float4*)&Bs[brow][bcol] = bv;
        __syncthreads();
        #pragma unroll
        for (int k = 0; k < BK; k++) {
            float a[4];
            #pragma unroll
            for (int i = 0; i < 4; i++) a[i] = As[ty * 4 + i][k];
            float4 b4 = *(const float4*)&Bs[k][tx * 4];
            #pragma unroll
            for (int i = 0; i < 4; i++) {
                acc[i][0] += a[i] * b4.x;
                acc[i][1] += a[i] * b4.y;
                acc[i][2] += a[i] * b4.z;
                acc[i][3] += a[i] * b4.w;
            }
        }
        __syncthreads();
    }

    #pragma unroll
    for (int i = 0; i < 4; i++) {
        int row = m0 + ty * 4 + i;
        int col0 = n0 + tx * 4;
        float4 o;
        float v[4];
        #pragma unroll
        for (int j = 0; j < 4; j++) {
            float x = acc[i][j];
            int col = col0 + j;
            if (EPI == EPI_SILU) {
                x = x / (1.0f + expf(-x));
            } else if (EPI == EPI_RES) {
                x = x + res[(size_t)row * N + col];
            } else if (EPI == EPI_BIAS_GELU) {
                x = x + bias[col];
                x = 0.5f * x * (1.0f + erff(x * 0.70710678118654752f));
            } else if (EPI == EPI_BIAS_RES) {
                x = x + bias[col] + res[(size_t)row * N + col];
            }
            v[j] = x;
        }
        o.x = v[0]; o.y = v[1]; o.z = v[2]; o.w = v[3];
        *(float4*)&C[(size_t)row * N + col0] = o;
    }
}

// ---------------- fused causal retention: per (b,h), 64-row blocks ----------------
#define QS_LD 132
#define SS_LD 68
#define ATT_SMEM ((2*64*QS_LD + 64*SS_LD) * (int)sizeof(float))   // 84992 B

__global__ void __launch_bounds__(256) attn_kernel(
    const float* __restrict__ Q, const float* __restrict__ Kt,
    const float* __restrict__ V, float* __restrict__ Yh,
    const float* __restrict__ powtab)
{
    extern __shared__ float sm[];
    float* Qs  = sm;                     // [64][132]
    float* KVs = sm + 64 * QS_LD;        // [64][132] (K then reused for V)
    float* Ss  = sm + 2 * 64 * QS_LD;    // [64][68]

    int tid = threadIdx.x;
    int tx = tid & 15, ty = tid >> 4;
    int bh = blockIdx.y;
    int b = bh >> 2;
    int h = bh & 3;
    int row0 = blockIdx.x * 64;
    const float* pw = powtab + h * SSEQ;

    int lr = tid >> 5;          // 0..7
    int le = (tid & 31) * 4;    // 0..124

    // load Q tile [64][128]
    #pragma unroll
    for (int i = 0; i < 8; i++) {
        int rr = lr + i * 8;
        float4 v = *(const float4*)&Q[((size_t)(b * SSEQ + row0 + rr) * HIDDEN) + h * HD + le];
        *(float4*)&Qs[rr * QS_LD + le] = v;
    }

    float racc[4][8] = {};

    for (int tb = 0; tb <= blockIdx.x; tb++) {
        int t0 = tb * 64;
        __syncthreads();   // previous SV reads of KVs done (and first iter: nothing)
        #pragma unroll
        for (int i = 0; i < 8; i++) {
            int rr = lr + i * 8;
            float4 v = *(const float4*)&Kt[((size_t)(b * SSEQ + t0 + rr) * HIDDEN) + h * HD + le];
            *(float4*)&KVs[rr * QS_LD + le] = v;
        }
        __syncthreads();

        // S = Q K^T (64x64, reduce over 128)
        float sacc[4][4] = {};
        #pragma unroll
        for (int e4 = 0; e4 < HD; e4 += 4) {
            float4 qv[4], kv[4];
            #pragma unroll
            for (int i = 0; i < 4; i++) qv[i] = *(const float4*)&Qs[(ty * 4 + i) * QS_LD + e4];
            #pragma unroll
            for (int j = 0; j < 4; j++) kv[j] = *(const float4*)&KVs[(tx * 4 + j) * QS_LD + e4];
            #pragma unroll
            for (int i = 0; i < 4; i++)
                #pragma unroll
                for (int j = 0; j < 4; j++)
                    sacc[i][j] += qv[i].x * kv[j].x + qv[i].y * kv[j].y
                                + qv[i].z * kv[j].z + qv[i].w * kv[j].w;
        }

        // causal decay mask, stage to smem
        #pragma unroll
        for (int i = 0; i < 4; i++) {
            int gr = row0 + ty * 4 + i;
            #pragma unroll
            for (int j = 0; j < 4; j++) {
                int gc = t0 + tx * 4 + j;
                int d = gr - gc;
                float val = (d >= 0) ? sacc[i][j] * pw[d] : 0.0f;
                Ss[(ty * 4 + i) * SS_LD + tx * 4 + j] = val;
            }
        }
        __syncthreads();   // Ss visible, KVs reads done -> safe to overwrite with V

        #pragma unroll
        for (int i = 0; i < 8; i++) {
            int rr = lr + i * 8;
            float4 v = *(const float4*)&V[((size_t)(b * SSEQ + t0 + rr) * HIDDEN) + h * HD + le];
            *(float4*)&KVs[rr * QS_LD + le] = v;
        }
        __syncthreads();

        // ret += S @ V  (thread covers rows ty*4+i, cols tx*8+j)
        #pragma unroll 4
        for (int t = 0; t < 64; t++) {
            float sv[4];
            #pragma unroll
            for (int i = 0; i < 4; i++) sv[i] = Ss[(ty * 4 + i) * SS_LD + t];
            float4 va = *(const float4*)&KVs[t * QS_LD + tx * 8];
            float4 vb = *(const float4*)&KVs[t * QS_LD + tx * 8 + 4];
            #pragma unroll
            for (int i = 0; i < 4; i++) {
                racc[i][0] += sv[i] * va.x; racc[i][1] += sv[i] * va.y;
                racc[i][2] += sv[i] * va.z; racc[i][3] += sv[i] * va.w;
                racc[i][4] += sv[i] * vb.x; racc[i][5] += sv[i] * vb.y;
                racc[i][6] += sv[i] * vb.z; racc[i][7] += sv[i] * vb.w;
            }
        }
    }

    // write Yh[b, s, h*128 + c]
    #pragma unroll
    for (int i = 0; i < 4; i++) {
        int gr = row0 + ty * 4 + i;
        size_t base = (size_t)(b * SSEQ + gr) * HIDDEN + h * HD + tx * 8;
        float4 o1, o2;
        o1.x = racc[i][0]; o1.y = racc[i][1]; o1.z = racc[i][2]; o1.w = racc[i][3];
        o2.x = racc[i][4]; o2.y = racc[i][5]; o2.z = racc[i][6]; o2.w = racc[i][7];
        *(float4*)&Yh[base] = o1;
        *(float4*)&Yh[base + 4] = o2;
    }
}

// ---------------- host orchestration ----------------
struct DevPtrs {
    float *X, *Xn, *Q, *K, *V, *Yh, *G, *P, *Y, *Yn, *F, *pw, *cu, *su, *cd, *sd;
};

static void get_ptrs(DevPtrs& p)
{
    cudaGetSymbolAddress((void**)&p.X,  g_X);
    cudaGetSymbolAddress((void**)&p.Xn, g_Xn);
    cudaGetSymbolAddress((void**)&p.Q,  g_Q);
    cudaGetSymbolAddress((void**)&p.K,  g_K);
    cudaGetSymbolAddress((void**)&p.V,  g_V);
    cudaGetSymbolAddress((void**)&p.Yh, g_Yh);
    cudaGetSymbolAddress((void**)&p.G,  g_G);
    cudaGetSymbolAddress((void**)&p.P,  g_P);
    cudaGetSymbolAddress((void**)&p.Y,  g_Y);
    cudaGetSymbolAddress((void**)&p.Yn, g_Yn);
    cudaGetSymbolAddress((void**)&p.F,  g_F);
    cudaGetSymbolAddress((void**)&p.pw, g_pow);
    cudaGetSymbolAddress((void**)&p.cu, g_cu);
    cudaGetSymbolAddress((void**)&p.su, g_su);
    cudaGetSymbolAddress((void**)&p.cd, g_cd);
    cudaGetSymbolAddress((void**)&p.sd, g_sd);
}

extern "C" void kernel_launch(void* const* d_in, const int* in_sizes, int n_in,
                              void* d_out, int out_size)
{
    DevPtrs p;
    get_ptrs(p);
    cudaFuncSetAttribute(attn_kernel, cudaFuncAttributeMaxDynamicSharedMemorySize, ATT_SMEM);

    const float* X    = (const float*)d_in[0];
    const float* Wq   = (const float*)d_in[1];
    const float* Wk   = (const float*)d_in[2];
    const float* Wv   = (const float*)d_in[3];
    const float* Wg   = (const float*)d_in[4];
    const float* Wo   = (const float*)d_in[5];
    const float* gnw  = (const float*)d_in[6];
    const float* gnb  = (const float*)d_in[7];
    const float* ln1w = (const float*)d_in[8];
    const float* ln1b = (const float*)d_in[9];
    const float* ln2w = (const float*)d_in[10];
    const float* ln2b = (const float*)d_in[11];
    const float* f1w  = (const float*)d_in[12];
    const float* f1b  = (const float*)d_in[13];
    const float* f2w  = (const float*)d_in[14];
    const float* f2b  = (const float*)d_in[15];

    cudaMemcpyAsync(p.X, X, (size_t)NROWS * HIDDEN * sizeof(float),
                    cudaMemcpyDeviceToDevice, 0);
    xpos_tables_kernel<<<(SSEQ * HD + 255) / 256, 256>>>(p.cu, p.su, p.cd, p.sd);
    pow_kernel<<<(HEADS * SSEQ + 255) / 256, 256>>>(p.pw);

    dim3 g512(HIDDEN / BN, NROWS / BM);   // (8, 64)
    dim3 gFFN(FFND / BN, NROWS / BM);     // (16, 64)
    dim3 gatt(SSEQ / 64, BB * HEADS);     // (32, 8)
    int nPairBlocks = (NROWS * 256 + 255) / 256;

    for (int i = 0; i < LAYERS; i++) {
        // Xn = LN1(X)
        ln_kernel<<<NROWS, 128>>>(p.X, ln1w + i * HIDDEN, ln1b + i * HIDDEN, p.Xn);
        // Q,K,V projections (per-head weight layout)
        sgemm_kernel<EPI_NONE><<<g512, 256>>>(p.Xn, Wq + (size_t)i * HEADS * HIDDEN * HD,
                                              p.Q, NROWS, HIDDEN, HIDDEN, 1, nullptr, nullptr);
        sgemm_kernel<EPI_NONE><<<g512, 256>>>(p.Xn, Wk + (size_t)i * HEADS * HIDDEN * HD,
                                              p.K, NROWS, HIDDEN, HIDDEN, 1, nullptr, nullptr);
        sgemm_kernel<EPI_NONE><<<g512, 256>>>(p.Xn, Wv + (size_t)i * HEADS * HIDDEN * HD,
                                              p.V, NROWS, HIDDEN, HIDDEN, 1, nullptr, nullptr);
        // xPos rotary (Q upscale, K downscale)
        xpos_apply_kernel<<<nPairBlocks, 256>>>(p.Q, p.cu, p.su);
        xpos_apply_kernel<<<nPairBlocks, 256>>>(p.K, p.cd, p.sd);
        // gate G = silu(Xn @ Wg)
        sgemm_kernel<EPI_SILU><<<g512, 256>>>(p.Xn, Wg + (size_t)i * HIDDEN * HIDDEN,
                                              p.G, NROWS, HIDDEN, HIDDEN, 0, nullptr, nullptr);
        // retention
        attn_kernel<<<gatt, 256, ATT_SMEM>>>(p.Q, p.K, p.V, p.Yh, p.pw);
        // P = gn(Yh) * G
        gn_gate_kernel<<<NROWS, 128>>>(p.Yh, gnw + i * HIDDEN, gnb + i * HIDDEN, p.G, p.P);
        // Y = P @ Wo + X
        sgemm_kernel<EPI_RES><<<g512, 256>>>(p.P, Wo + (size_t)i * HIDDEN * HIDDEN,
                                             p.Y, NROWS, HIDDEN, HIDDEN, 0, nullptr, p.X);
        // Yn = LN2(Y)
        ln_kernel<<<NROWS, 128>>>(p.Y, ln2w + i * HIDDEN, ln2b + i * HIDDEN, p.Yn);
        // F = gelu(Yn @ f1 + b1)
        sgemm_kernel<EPI_BIAS_GELU><<<gFFN, 256>>>(p.Yn, f1w + (size_t)i * HIDDEN * FFND,
                                                   p.F, NROWS, FFND, HIDDEN, 0,
                                                   f1b + i * FFND, nullptr);
        // X = F @ f2 + b2 + Y
        float* outp = (i == LAYERS - 1) ? (float*)d_out : p.X;
        sgemm_kernel<EPI_BIAS_RES><<<g512, 256>>>(p.F, f2w + (size_t)i * FFND * HIDDEN,
                                                  outp, NROWS, HIDDEN, FFND, 0,
                                                  f2b + i * HIDDEN, p.Y);
    }
}